// round 7
// baseline (speedup 1.0000x reference)
#include <cuda_runtime.h>
#include <math.h>

// Problem constants (fixed shapes per reference)
#define BDIM    512          // number of events (scan length)
#define DEG     16           // neighbors per event
#define NSLOT   17           // write slots per step: w=0 event, w=1..16 neighbors
#define NREAD   22           // read slots per step: 17 (u) + 5 (u_neg)
#define NEGK    5
#define H       256
#define NNODES  200000
#define HBITS   15
#define HSIZE   (1 << HBITS)
#define HMASK   (HSIZE - 1)
#define HK      16           // max writers tracked per row
#define CPR     256          // z0-copy rows per work chunk
#define NCHUNK  ((NNODES + CPR - 1) / CPR)     // 782
#define NTHR    256
#define FULLMASK 0x1FFFF                        // all 17 slots done

// ------------------------- persistent device state -------------------------
__device__ __align__(16) float g_staging[BDIM][NSLOT][H];   // 8.9 MB
__device__ int g_done[BDIM];           // bitmask of completed slots (17 bits)
__device__ int g_needed[BDIM];         // bitmask of slots some future step reads
__device__ int g_src[BDIM][NREAD];     // -1 => z0[row], else (t'<<5)|w'
__device__ int g_ctr_step;
__device__ int g_ctr_copy;
__device__ int g_hrow[HSIZE];
__device__ int g_hcnt[HSIZE];
__device__ int g_hent[HSIZE][HK];      // e = (t<<10)|(prio<<5)|w

// ------------------------------- helpers -----------------------------------
__device__ __forceinline__ unsigned hashrow(int row) {
    return ((unsigned)row * 2654435761u) >> (32 - HBITS);
}
__device__ __forceinline__ int ld_acq(const int* p) {
    int v; asm volatile("ld.acquire.gpu.b32 %0, [%1];" : "=r"(v) : "l"(p) : "memory"); return v;
}
__device__ __forceinline__ void red_or_rel(int* p, int v) {
    asm volatile("red.release.gpu.global.or.b32 [%0], %1;" :: "l"(p), "r"(v) : "memory");
}
__device__ __forceinline__ void prefetch_l2(const void* p) {
    asm volatile("prefetch.global.L2 [%0];" :: "l"(p));
}
__device__ __forceinline__ void upk2(unsigned long long v, float& lo, float& hi) {
    asm("mov.b64 {%0, %1}, %2;" : "=f"(lo), "=f"(hi) : "l"(v));
}
// packed fp32x2 FMA: d = a*b + d
__device__ __forceinline__ void fma2(unsigned long long& d, unsigned long long a, unsigned long long b) {
    asm("fma.rn.f32x2 %0, %1, %2, %0;" : "+l"(d) : "l"(a), "l"(b));
}
__device__ __forceinline__ float sigmoidf_(float x) { return 1.0f / (1.0f + expf(-x)); }

// High-MLP matvec: dot(W[h,:], vec_smem) with 16 LDG.128 in flight per batch.
__device__ __forceinline__ float matvec_row(const float* __restrict__ W, int h,
                                            const float* __restrict__ vec_smem) {
    const ulonglong2* wp = (const ulonglong2*)(W + (size_t)h * H);
    const ulonglong2* v  = (const ulonglong2*)vec_smem;
    unsigned long long acc = 0ull;
    #pragma unroll
    for (int b = 0; b < 4; ++b) {
        ulonglong2 w[16];
        #pragma unroll
        for (int i = 0; i < 16; ++i) w[i] = wp[b * 16 + i];
        #pragma unroll
        for (int i = 0; i < 16; ++i) {
            fma2(acc, w[i].x, v[b * 16 + i].x);
            fma2(acc, w[i].y, v[b * 16 + i].y);
        }
    }
    float lo, hi; upk2(acc, lo, hi);
    return lo + hi;
}

// ------------------------------- kernels -----------------------------------
__global__ void k_clear() {
    int i = blockIdx.x * blockDim.x + threadIdx.x;
    if (i < HSIZE) { g_hrow[i] = -1; g_hcnt[i] = 0; }
    if (i < BDIM) { g_done[i] = 0; g_needed[i] = 0; }
    if (i == 0) { g_ctr_step = 0; g_ctr_copy = 0; }
}

// Insert the 512*17 writes into the hash; prefetch the 1MB weight set to L2.
__global__ void k_insert(const int* __restrict__ u,
                         const float* __restrict__ Wh,  const float* __restrict__ We2n,
                         const float* __restrict__ Wre, const float* __restrict__ Wrn) {
    int idx = blockIdx.x * blockDim.x + threadIdx.x;
    if (idx < 8192) {                              // 8192 x 128B lines = 1MB of weights
        int m = idx >> 11, l = idx & 2047;
        const float* base = (m == 0) ? Wh : (m == 1) ? We2n : (m == 2) ? Wre : Wrn;
        prefetch_l2(base + l * 32);
    }
    if (idx >= BDIM * NSLOT) return;
    int t = idx / NSLOT, w = idx % NSLOT;
    int row = u[t * NSLOT + w];
    int prio = (w == 0) ? 16 : (w - 1);            // event applied last; later neighbor wins
    int e = (t << 10) | (prio << 5) | w;
    unsigned hsh = hashrow(row);
    for (;;) {
        int cur = atomicCAS(&g_hrow[hsh], -1, row);
        if (cur == -1 || cur == row) {
            int c = atomicAdd(&g_hcnt[hsh], 1);
            if (c < HK) g_hent[hsh][c] = e;
            break;
        }
        hsh = (hsh + 1) & HMASK;
    }
}

// Resolve read versions; mark needed producer slots; prefetch z0 rows etc.
__global__ void k_resolve(const int* __restrict__ u, const int* __restrict__ u_neg,
                          const float* __restrict__ z0, const float* __restrict__ time_bar,
                          const float* __restrict__ td) {
    int idx = blockIdx.x * blockDim.x + threadIdx.x;
    if (idx < 1088) prefetch_l2(td + idx * 32);    // whole td array
    if (idx >= BDIM * NREAD) return;
    int t = idx / NREAD, r = idx % NREAD;
    int row = (r < NSLOT) ? u[t * NSLOT + r] : u_neg[t * NEGK + (r - NSLOT)];
    if (r >= NSLOT) prefetch_l2(time_bar + (size_t)t * NNODES + row);
    unsigned hsh = hashrow(row);
    int src = -1, bestkey = -1;
    for (;;) {
        int cur = g_hrow[hsh];
        if (cur == -1) break;
        if (cur == row) {
            int c = g_hcnt[hsh]; if (c > HK) c = HK;
            for (int i = 0; i < c; ++i) {
                int e = g_hent[hsh][i];
                if ((e >> 10) < t) {
                    int key = e >> 5;
                    if (key > bestkey) { bestkey = key; src = ((e >> 10) << 5) | (e & 31); }
                }
            }
            break;
        }
        hsh = (hsh + 1) & HMASK;
    }
    g_src[t][r] = src;
    if (src >= 0) {
        atomicOr(&g_needed[src >> 5], 1 << (src & 31));  // producer publishes this slot early
    } else {                                       // prefetch the z0 row (1KB = 8 lines)
        const float* p = z0 + (size_t)row * H;
        #pragma unroll
        for (int l = 0; l < 8; ++l) prefetch_l2(p + l * 32);
    }
}

// Persistent main kernel: 256 threads/CTA, 2 CTAs/SM.
// Pool A (blockIdx < nsm): event steps. Pool B: z0->out copy chunks from t=0.
// Pools steal from each other when their own counter is exhausted.
__global__ void __launch_bounds__(NTHR, 2) k_main(
    const int* __restrict__ u, const float* __restrict__ td,
    const int* __restrict__ u_neg, const float* __restrict__ z0,
    const float* __restrict__ Wh,   const float* __restrict__ bh,
    const float* __restrict__ We2n, const float* __restrict__ be2n,
    const float* __restrict__ Wre,  const float* __restrict__ bre,
    const float* __restrict__ Wrn,  const float* __restrict__ brn,
    const float* __restrict__ Wt,   const float* __restrict__ bt,
    float* __restrict__ out, int nsm)
{
    __shared__ __align__(16) float s_znb[DEG][H];
    __shared__ __align__(16) float s_emb[H];
    __shared__ __align__(16) float s_mean[H];
    __shared__ float s_td[NSLOT][4];
    __shared__ int s_id;

    const int tid  = threadIdx.x;              // == h (output column)
    const int lane = tid & 31, wid = tid >> 5;
    float* outz = out + (BDIM + BDIM * NEGK);

    int mode = (blockIdx.x < nsm) ? 0 : 1;     // 0=steps, 1=copy (tid 0 only uses it)

    for (;;) {
        __syncthreads();                      // protect s_id / smem reuse
        if (tid == 0) {
            int id = -1;
            #pragma unroll
            for (int tries = 0; tries < 2 && id < 0; ++tries) {
                if (mode == 0) {
                    int v = atomicAdd(&g_ctr_step, 1);
                    if (v < BDIM) id = v; else mode = 1;
                } else {
                    int v = atomicAdd(&g_ctr_copy, 1);
                    if (v < NCHUNK) id = BDIM + v; else mode = 0;
                }
            }
            s_id = id;
        }
        __syncthreads();
        const int id = s_id;
        if (id < 0) break;

        if (id >= BDIM) {
            // ---- streaming copy chunk: z0 rows -> z_final region of out ----
            int chunk = id - BDIM;
            size_t r0 = (size_t)chunk * CPR;
            int nrow = (NNODES - (int)r0 > CPR) ? CPR : (NNODES - (int)r0);
            const float4* src = (const float4*)z0 + r0 * (H / 4);
            float4*       dst = (float4*)outz  + r0 * (H / 4);
            int n4 = nrow * (H / 4);
            for (int base = 0; base < n4; base += NTHR * 8) {
                float4 t[8];
                #pragma unroll
                for (int b = 0; b < 8; ++b) {
                    int i = base + tid + b * NTHR;
                    if (i < n4) t[b] = __ldcs(&src[i]);
                }
                #pragma unroll
                for (int b = 0; b < 8; ++b) {
                    int i = base + tid + b * NTHR;
                    if (i < n4) __stcs(&dst[i], t[b]);
                }
            }
            continue;
        }

        // ---------------- step s ----------------
        const int s = id;

        if (tid < NREAD) {                       // wait for producer SLOTS (bitwise)
            int sv = g_src[s][tid];
            if (sv >= 0) {
                int* flag = &g_done[sv >> 5];
                int bit = 1 << (sv & 31);
                while (!(ld_acq(flag) & bit)) __nanosleep(32);
            }
        }
        if (tid >= 32 && tid < 32 + NSLOT * 4) { // normalized time deltas
            int q = tid - 32;
            const float inv_sd[4] = {1.f/50.f, 1.f/7.f, 1.f/15.f, 1.f/15.f};
            s_td[q >> 2][q & 3] = td[(s * NSLOT + (q >> 2)) * 4 + (q & 3)] * inv_sd[q & 3];
        }
        __syncthreads();

        // load the 17 rows (emb_u + 16 neighbors); one warp per row
        for (int r = wid; r < NSLOT; r += 8) {
            int sv = g_src[s][r];
            const float4* src4 = (sv >= 0)
                ? (const float4*)g_staging[sv >> 5][sv & 31]
                : (const float4*)(z0 + (size_t)u[s * NSLOT + r] * H);
            float4* dst4 = (r == 0) ? (float4*)s_emb : (float4*)s_znb[r - 1];
            dst4[lane]      = src4[lane];
            dst4[lane + 32] = src4[lane + 32];
        }
        __syncthreads();

        // mean over 16 neighbor rows
        {
            float acc = 0.f;
            #pragma unroll
            for (int j = 0; j < DEG; ++j) acc += s_znb[j][tid];
            s_mean[tid] = acc * (1.0f / DEG);
        }
        __syncthreads();

        const int h = tid;
        const int need = g_needed[s];            // slots some future step reads
        float4 wtr = *(const float4*)(Wt + (size_t)h * 4);
        float btv = bt[h];

        // cmn = (We2n*emb)[h] + be2n + brn  (needed by all z_nb rows)
        float cmn = matvec_row(We2n, h, s_emb) + be2n[h] + brn[h];
        bool zev_done = false;

        // ---------- PHASE 1: compute & publish only the needed slots ----------
        if (need) {
            if (need & 1) {                      // z_ev
                float ah = matvec_row(Wh,  h, s_mean);
                float ae = matvec_row(Wre, h, s_emb);
                float tf0 = btv + wtr.x*s_td[0][0] + wtr.y*s_td[0][1]
                                + wtr.z*s_td[0][2] + wtr.w*s_td[0][3];
                g_staging[s][0][h] = sigmoidf_(ah + bh[h] + ae + bre[h] + tf0);
                zev_done = true;
            }
            for (int m = (need >> 1) & 0xFFFF; m; m &= (m - 1)) {
                int j = __ffs(m) - 1;            // needed neighbor row
                float d = matvec_row(Wrn, h, s_znb[j]);
                float tf = btv + wtr.x*s_td[1+j][0] + wtr.y*s_td[1+j][1]
                               + wtr.z*s_td[1+j][2] + wtr.w*s_td[1+j][3];
                g_staging[s][1 + j][h] = sigmoidf_(d + cmn + tf);
            }
            __syncthreads();
            if (tid == 0) red_or_rel(&g_done[s], need);
        }

        // ---------- PHASE 2: remaining slots ----------
        if (!zev_done) {
            float ah = matvec_row(Wh,  h, s_mean);
            float ae = matvec_row(Wre, h, s_emb);
            float tf0 = btv + wtr.x*s_td[0][0] + wtr.y*s_td[0][1]
                            + wtr.z*s_td[0][2] + wtr.w*s_td[0][3];
            g_staging[s][0][h] = sigmoidf_(ah + bh[h] + ae + bre[h] + tf0);
        }
        {
            // GEMM over all 16 j
            unsigned long long acc2[DEG];
            #pragma unroll
            for (int j = 0; j < DEG; ++j) acc2[j] = 0ull;
            const ulonglong2* wp = (const ulonglong2*)(Wrn + (size_t)h * H);
            ulonglong2 w = wp[0];
            #pragma unroll 4
            for (int i4 = 0; i4 < H / 4; ++i4) {
                ulonglong2 wn = (i4 < H / 4 - 1) ? wp[i4 + 1] : w;   // prefetch next
                #pragma unroll
                for (int j = 0; j < DEG; ++j) {
                    ulonglong2 z = *(const ulonglong2*)&s_znb[j][i4 * 4];  // LDS.128 bcast
                    fma2(acc2[j], w.x, z.x);
                    fma2(acc2[j], w.y, z.y);
                }
                w = wn;
            }
            int skip = need >> 1;
            #pragma unroll
            for (int j = 0; j < DEG; ++j) {
                if (!((skip >> j) & 1)) {
                    float lo, hi; upk2(acc2[j], lo, hi);
                    float tf = btv + wtr.x*s_td[1+j][0] + wtr.y*s_td[1+j][1]
                                   + wtr.z*s_td[1+j][2] + wtr.w*s_td[1+j][3];
                    g_staging[s][1 + j][h] = sigmoidf_(lo + hi + cmn + tf);
                }
            }
        }
        __syncthreads();
        if (tid == 0) red_or_rel(&g_done[s], FULLMASK);
    }
}

// Post pass: one block per step. Hawkes lambdas (pos + 5 neg) and final scatter
// of last-writer rows over the copied z0 region.
__global__ void __launch_bounds__(NTHR) k_post(
    const int* __restrict__ u, const int* __restrict__ u_neg,
    const float* __restrict__ time_bar, const float* __restrict__ time_cur,
    const float* __restrict__ td, const float* __restrict__ z0,
    const float* __restrict__ Wom, const float* __restrict__ bom_p,
    const float* __restrict__ wt_p, const float* __restrict__ alpha_p,
    const float* __restrict__ psi_p, float* __restrict__ out)
{
    const int s = blockIdx.x;
    const int tid = threadIdx.x, lane = tid & 31, wid = tid >> 5;
    const float w_t = *wt_p, alpha = *alpha_p, psi = *psi_p, bom = *bom_p;
    const float inv_psi = 1.0f / (psi + 1e-7f);
    float* outz = out + (BDIM + BDIM * NEGK);

    if (wid < NEGK) {                            // negative lambdas
        int node = u_neg[s * NEGK + wid];
        int sv = g_src[s][NSLOT + wid];
        const float* srcp = (sv >= 0) ? g_staging[sv >> 5][sv & 31]
                                      : (z0 + (size_t)node * H);
        float acc = 0.f;
        for (int i = lane; i < H; i += 32) acc += srcp[i] * Wom[i];
        #pragma unroll
        for (int o = 16; o; o >>= 1) acc += __shfl_down_sync(0xffffffffu, acc, o);
        if (lane == 0) {
            float ts = time_cur[s] - time_bar[(size_t)s * NNODES + node];
            float g = acc + bom + alpha * expf(-w_t * (ts * (1.0f / 86400.0f)));
            float gp = fminf(fmaxf(g * inv_psi, -75.f), 75.f);
            out[BDIM + s * NEGK + wid] = psi * log1pf(expf(gp)) * (1.0f / NEGK);
        }
    } else if (wid == 5) {                       // positive lambda
        int sv = g_src[s][0];
        const float* srcp = (sv >= 0) ? g_staging[sv >> 5][sv & 31]
                                      : (z0 + (size_t)u[s * NSLOT] * H);
        float acc = 0.f;
        for (int i = lane; i < H; i += 32) acc += srcp[i] * Wom[i];
        #pragma unroll
        for (int o = 16; o; o >>= 1) acc += __shfl_down_sync(0xffffffffu, acc, o);
        if (lane == 0) {
            float ts = time_cur[s] - td[s * NSLOT * 4] * (1.0f / 50.0f);
            float g = acc + bom + alpha * expf(-w_t * (ts * (1.0f / 86400.0f)));
            float gp = fminf(fmaxf(g * inv_psi, -75.f), 75.f);
            out[s] = psi * log1pf(expf(gp));
        }
    }

    // scatter: warp handles slots wid, wid+8, wid+16
    for (int w = wid; w < NSLOT; w += 8) {
        int row = u[s * NSLOT + w];
        unsigned hsh = hashrow(row);
        int beste = -1, bestkey = -1;
        for (;;) {
            int cur = g_hrow[hsh];
            if (cur == -1) break;
            if (cur == row) {
                int c = g_hcnt[hsh]; if (c > HK) c = HK;
                for (int i = 0; i < c; ++i) {
                    int e = g_hent[hsh][i];
                    int key = e >> 5;
                    if (key > bestkey) { bestkey = key; beste = e; }
                }
                break;
            }
            hsh = (hsh + 1) & HMASK;
        }
        int prio = (w == 0) ? 16 : (w - 1);
        if (beste == ((s << 10) | (prio << 5) | w)) {   // this (s,w) is the last writer
            const float4* src = (const float4*)g_staging[s][w];
            float4* dst = (float4*)outz + (size_t)row * (H / 4);
            dst[lane]      = src[lane];
            dst[lane + 32] = src[lane + 32];
        }
    }
}

// ------------------------------- launch ------------------------------------
extern "C" void kernel_launch(void* const* d_in, const int* in_sizes, int n_in,
                              void* d_out, int out_size) {
    const int*   u     = (const int*)  d_in[0];
    const float* td    = (const float*)d_in[1];
    const float* tbar  = (const float*)d_in[2];
    const float* tcur  = (const float*)d_in[3];
    // d_in[4] significance, d_in[5] magnitudo: unused by reference
    const int*   uneg  = (const int*)  d_in[6];
    const float* z0    = (const float*)d_in[7];
    const float* Wh    = (const float*)d_in[8];
    const float* bh    = (const float*)d_in[9];
    const float* We2n  = (const float*)d_in[10];
    const float* be2n  = (const float*)d_in[11];
    const float* Wre   = (const float*)d_in[12];
    const float* bre   = (const float*)d_in[13];
    const float* Wrn   = (const float*)d_in[14];
    const float* brn   = (const float*)d_in[15];
    const float* Wt    = (const float*)d_in[16];
    const float* bt    = (const float*)d_in[17];
    const float* Wom   = (const float*)d_in[18];
    const float* bom   = (const float*)d_in[19];
    const float* wt    = (const float*)d_in[20];
    const float* alpha = (const float*)d_in[21];
    const float* psi   = (const float*)d_in[22];
    float* out = (float*)d_out;

    k_clear  <<<(HSIZE + 255) / 256, 256>>>();
    k_insert <<<(BDIM * NSLOT + 255) / 256, 256>>>(u, Wh, We2n, Wre, Wrn);
    k_resolve<<<(BDIM * NREAD + 255) / 256, 256>>>(u, uneg, z0, tbar, td);

    int dev = 0, nsm = 148;
    cudaGetDevice(&dev);
    cudaDeviceGetAttribute(&nsm, cudaDevAttrMultiProcessorCount, dev);

    k_main<<<nsm * 2, NTHR>>>(u, td, uneg, z0,
                              Wh, bh, We2n, be2n, Wre, bre, Wrn, brn,
                              Wt, bt, out, nsm);

    k_post<<<BDIM, NTHR>>>(u, uneg, tbar, tcur, td, z0,
                           Wom, bom, wt, alpha, psi, out);
}

// round 8
// speedup vs baseline: 1.7615x; 1.7615x over previous
#include <cuda_runtime.h>
#include <math.h>

// Problem constants (fixed shapes per reference)
#define BDIM    512          // number of events (scan length)
#define DEG     16           // neighbors per event
#define NSLOT   17           // write slots per step: w=0 event, w=1..16 neighbors
#define NREAD   22           // read slots per step: 17 (u) + 5 (u_neg)
#define NEGK    5
#define H       256
#define NNODES  200000
#define HBITS   15
#define HSIZE   (1 << HBITS)
#define HMASK   (HSIZE - 1)
#define HK      16           // max writers tracked per row
#define CPR     256          // z0-copy rows per work chunk
#define NCHUNK  ((NNODES + CPR - 1) / CPR)     // 782
#define TOTAL_WORK (BDIM + NCHUNK)             // steps first, then copies
#define NTHR    256
#define FULLMASK 0x1FFFF                        // all 17 slots done

// ------------------------- persistent device state -------------------------
__device__ __align__(16) float g_staging[BDIM][NSLOT][H];   // 8.9 MB
// Blocked-transposed weights: g_BT[m][i4*H + h] = float4(W_m[h][4*i4 .. 4*i4+3])
// m: 0=Wh, 1=We2n, 2=Wre, 3=Wrn. Coalesced per-warp weight loads (nL=4 not 32).
__device__ __align__(16) float4 g_BT[4][ (H/4) * H ];       // 1 MB
__device__ int g_done[BDIM];           // bitmask of completed slots (17 bits)
__device__ int g_needed[BDIM];         // bitmask of slots some future step reads
__device__ int g_src[BDIM][NREAD];     // -1 => z0[row], else (t'<<5)|w'
__device__ int g_ctr;
__device__ int g_hrow[HSIZE];
__device__ int g_hcnt[HSIZE];
__device__ int g_hent[HSIZE][HK];      // e = (t<<10)|(prio<<5)|w

// ------------------------------- helpers -----------------------------------
__device__ __forceinline__ unsigned hashrow(int row) {
    return ((unsigned)row * 2654435761u) >> (32 - HBITS);
}
__device__ __forceinline__ int ld_acq(const int* p) {
    int v; asm volatile("ld.acquire.gpu.b32 %0, [%1];" : "=r"(v) : "l"(p) : "memory"); return v;
}
__device__ __forceinline__ void red_or_rel(int* p, int v) {
    asm volatile("red.release.gpu.global.or.b32 [%0], %1;" :: "l"(p), "r"(v) : "memory");
}
__device__ __forceinline__ void prefetch_l2(const void* p) {
    asm volatile("prefetch.global.L2 [%0];" :: "l"(p));
}
__device__ __forceinline__ void upk2(unsigned long long v, float& lo, float& hi) {
    asm("mov.b64 {%0, %1}, %2;" : "=f"(lo), "=f"(hi) : "l"(v));
}
// packed fp32x2 FMA: d = a*b + d
__device__ __forceinline__ void fma2(unsigned long long& d, unsigned long long a, unsigned long long b) {
    asm("fma.rn.f32x2 %0, %1, %2, %0;" : "+l"(d) : "l"(a), "l"(b));
}
__device__ __forceinline__ float sigmoidf_(float x) { return 1.0f / (1.0f + expf(-x)); }

// Coalesced high-MLP matvec using blocked-transposed weights.
// dot(W[h,:], v) = sum_i4 BT[i4*H + h] . v4[i4]; warp-coalesced LDG.128.
__device__ __forceinline__ float matvec_bt(const ulonglong2* __restrict__ BT2, int h,
                                           const float* __restrict__ vec_smem) {
    const ulonglong2* v = (const ulonglong2*)vec_smem;
    unsigned long long acc = 0ull;
    #pragma unroll
    for (int b = 0; b < 4; ++b) {
        ulonglong2 w[16];
        #pragma unroll
        for (int i = 0; i < 16; ++i) w[i] = BT2[(b * 16 + i) * H + h];
        #pragma unroll
        for (int i = 0; i < 16; ++i) {
            fma2(acc, w[i].x, v[b * 16 + i].x);
            fma2(acc, w[i].y, v[b * 16 + i].y);
        }
    }
    float lo, hi; upk2(acc, lo, hi);
    return lo + hi;
}

// ------------------------------- kernels -----------------------------------
__global__ void k_clear() {
    int i = blockIdx.x * blockDim.x + threadIdx.x;
    if (i < HSIZE) { g_hrow[i] = -1; g_hcnt[i] = 0; }
    if (i < BDIM) { g_done[i] = 0; g_needed[i] = 0; }
    if (i == 0) g_ctr = 0;
}

// Build blocked-transposed weights (one-time, ~1MB; writes leave BT hot in L2).
__global__ void k_transpose(const float* __restrict__ Wh,  const float* __restrict__ We2n,
                            const float* __restrict__ Wre, const float* __restrict__ Wrn) {
    int idx = blockIdx.x * blockDim.x + threadIdx.x;   // 4 * 64 * 256 = 65536
    int m = idx >> 14, rem = idx & 16383;
    int i4 = rem >> 8, h = rem & 255;
    const float* W = (m == 0) ? Wh : (m == 1) ? We2n : (m == 2) ? Wre : Wrn;
    g_BT[m][i4 * H + h] = *(const float4*)(W + (size_t)h * H + i4 * 4);
}

// Insert the 512*17 writes into the hash.
__global__ void k_insert(const int* __restrict__ u) {
    int idx = blockIdx.x * blockDim.x + threadIdx.x;
    if (idx >= BDIM * NSLOT) return;
    int t = idx / NSLOT, w = idx % NSLOT;
    int row = u[t * NSLOT + w];
    int prio = (w == 0) ? 16 : (w - 1);            // event applied last; later neighbor wins
    int e = (t << 10) | (prio << 5) | w;
    unsigned hsh = hashrow(row);
    for (;;) {
        int cur = atomicCAS(&g_hrow[hsh], -1, row);
        if (cur == -1 || cur == row) {
            int c = atomicAdd(&g_hcnt[hsh], 1);
            if (c < HK) g_hent[hsh][c] = e;
            break;
        }
        hsh = (hsh + 1) & HMASK;
    }
}

// Resolve read versions; mark needed producer slots; prefetch z0 rows etc.
__global__ void k_resolve(const int* __restrict__ u, const int* __restrict__ u_neg,
                          const float* __restrict__ z0, const float* __restrict__ time_bar,
                          const float* __restrict__ td) {
    int idx = blockIdx.x * blockDim.x + threadIdx.x;
    if (idx < 1088) prefetch_l2(td + idx * 32);    // whole td array
    if (idx >= BDIM * NREAD) return;
    int t = idx / NREAD, r = idx % NREAD;
    int row = (r < NSLOT) ? u[t * NSLOT + r] : u_neg[t * NEGK + (r - NSLOT)];
    if (r >= NSLOT) prefetch_l2(time_bar + (size_t)t * NNODES + row);
    unsigned hsh = hashrow(row);
    int src = -1, bestkey = -1;
    for (;;) {
        int cur = g_hrow[hsh];
        if (cur == -1) break;
        if (cur == row) {
            int c = g_hcnt[hsh]; if (c > HK) c = HK;
            for (int i = 0; i < c; ++i) {
                int e = g_hent[hsh][i];
                if ((e >> 10) < t) {
                    int key = e >> 5;
                    if (key > bestkey) { bestkey = key; src = ((e >> 10) << 5) | (e & 31); }
                }
            }
            break;
        }
        hsh = (hsh + 1) & HMASK;
    }
    g_src[t][r] = src;
    if (src >= 0) {
        atomicOr(&g_needed[src >> 5], 1 << (src & 31));  // producer publishes this slot early
    } else {                                       // prefetch the z0 row (1KB = 8 lines)
        const float* p = z0 + (size_t)row * H;
        #pragma unroll
        for (int l = 0; l < 8; ++l) prefetch_l2(p + l * 32);
    }
}

// Persistent main kernel: 256 threads/CTA, 2 CTAs/SM, single work counter.
// ids [0,512): steps. [512,...): z0 -> out copy chunks (fill chain-wait tails).
__global__ void __launch_bounds__(NTHR, 2) k_main(
    const int* __restrict__ u, const float* __restrict__ td,
    const float* __restrict__ z0,
    const float* __restrict__ bh,  const float* __restrict__ be2n,
    const float* __restrict__ bre, const float* __restrict__ brn,
    const float* __restrict__ Wt,  const float* __restrict__ bt,
    float* __restrict__ out)
{
    __shared__ __align__(16) float s_znb[DEG][H];
    __shared__ __align__(16) float s_emb[H];
    __shared__ __align__(16) float s_mean[H];
    __shared__ float s_td[NSLOT][4];
    __shared__ int s_id;

    const int tid  = threadIdx.x;              // == h (output column)
    const int lane = tid & 31, wid = tid >> 5;
    float* outz = out + (BDIM + BDIM * NEGK);

    const ulonglong2* BT_h   = (const ulonglong2*)g_BT[0];
    const ulonglong2* BT_e2n = (const ulonglong2*)g_BT[1];
    const ulonglong2* BT_re  = (const ulonglong2*)g_BT[2];
    const ulonglong2* BT_rn  = (const ulonglong2*)g_BT[3];

    for (;;) {
        __syncthreads();                      // protect s_id / smem reuse
        if (tid == 0) s_id = atomicAdd(&g_ctr, 1);
        __syncthreads();
        const int id = s_id;
        if (id >= TOTAL_WORK) break;

        if (id >= BDIM) {
            // ---- streaming copy chunk: z0 rows -> z_final region of out ----
            int chunk = id - BDIM;
            size_t r0 = (size_t)chunk * CPR;
            int nrow = (NNODES - (int)r0 > CPR) ? CPR : (NNODES - (int)r0);
            const float4* src = (const float4*)z0 + r0 * (H / 4);
            float4*       dst = (float4*)outz  + r0 * (H / 4);
            int n4 = nrow * (H / 4);
            for (int base = 0; base < n4; base += NTHR * 8) {
                float4 t[8];
                #pragma unroll
                for (int b = 0; b < 8; ++b) {
                    int i = base + tid + b * NTHR;
                    if (i < n4) t[b] = __ldcs(&src[i]);
                }
                #pragma unroll
                for (int b = 0; b < 8; ++b) {
                    int i = base + tid + b * NTHR;
                    if (i < n4) __stcs(&dst[i], t[b]);
                }
            }
            continue;
        }

        // ---------------- step s ----------------
        const int s = id;

        if (tid < NREAD) {                       // wait for producer SLOTS (bitwise)
            int sv = g_src[s][tid];
            if (sv >= 0) {
                int* flag = &g_done[sv >> 5];
                int bit = 1 << (sv & 31);
                while (!(ld_acq(flag) & bit)) __nanosleep(32);
            }
        }
        if (tid >= 32 && tid < 32 + NSLOT * 4) { // normalized time deltas
            int q = tid - 32;
            const float inv_sd[4] = {1.f/50.f, 1.f/7.f, 1.f/15.f, 1.f/15.f};
            s_td[q >> 2][q & 3] = td[(s * NSLOT + (q >> 2)) * 4 + (q & 3)] * inv_sd[q & 3];
        }
        __syncthreads();

        // load the 17 rows (emb_u + 16 neighbors); one warp per row
        for (int r = wid; r < NSLOT; r += 8) {
            int sv = g_src[s][r];
            const float4* src4 = (sv >= 0)
                ? (const float4*)g_staging[sv >> 5][sv & 31]
                : (const float4*)(z0 + (size_t)u[s * NSLOT + r] * H);
            float4* dst4 = (r == 0) ? (float4*)s_emb : (float4*)s_znb[r - 1];
            dst4[lane]      = src4[lane];
            dst4[lane + 32] = src4[lane + 32];
        }
        __syncthreads();

        // mean over 16 neighbor rows
        {
            float acc = 0.f;
            #pragma unroll
            for (int j = 0; j < DEG; ++j) acc += s_znb[j][tid];
            s_mean[tid] = acc * (1.0f / DEG);
        }
        __syncthreads();

        const int h = tid;
        const int need = g_needed[s];            // slots some future step reads
        float4 wtr = *(const float4*)(Wt + (size_t)h * 4);
        float btv = bt[h];

        // cmn = (We2n*emb)[h] + be2n + brn  (needed by all z_nb rows)
        float cmn = matvec_bt(BT_e2n, h, s_emb) + be2n[h] + brn[h];
        bool zev_done = false;

        // ---------- PHASE 1: compute & publish only the needed slots ----------
        if (need) {
            if (need & 1) {                      // z_ev
                float ah = matvec_bt(BT_h,  h, s_mean);
                float ae = matvec_bt(BT_re, h, s_emb);
                float tf0 = btv + wtr.x*s_td[0][0] + wtr.y*s_td[0][1]
                                + wtr.z*s_td[0][2] + wtr.w*s_td[0][3];
                g_staging[s][0][h] = sigmoidf_(ah + bh[h] + ae + bre[h] + tf0);
                zev_done = true;
            }
            for (int m = (need >> 1) & 0xFFFF; m; m &= (m - 1)) {
                int j = __ffs(m) - 1;            // needed neighbor row
                float d = matvec_bt(BT_rn, h, s_znb[j]);
                float tf = btv + wtr.x*s_td[1+j][0] + wtr.y*s_td[1+j][1]
                               + wtr.z*s_td[1+j][2] + wtr.w*s_td[1+j][3];
                g_staging[s][1 + j][h] = sigmoidf_(d + cmn + tf);
            }
            __syncthreads();
            if (tid == 0) red_or_rel(&g_done[s], need);
        }

        // ---------- PHASE 2: remaining slots ----------
        if (!zev_done) {
            float ah = matvec_bt(BT_h,  h, s_mean);
            float ae = matvec_bt(BT_re, h, s_emb);
            float tf0 = btv + wtr.x*s_td[0][0] + wtr.y*s_td[0][1]
                            + wtr.z*s_td[0][2] + wtr.w*s_td[0][3];
            g_staging[s][0][h] = sigmoidf_(ah + bh[h] + ae + bre[h] + tf0);
        }
        {
            // GEMM over all 16 j; coalesced weight stream via BT_rn
            unsigned long long acc2[DEG];
            #pragma unroll
            for (int j = 0; j < DEG; ++j) acc2[j] = 0ull;
            ulonglong2 w = BT_rn[h];
            #pragma unroll 4
            for (int i4 = 0; i4 < H / 4; ++i4) {
                ulonglong2 wn = (i4 < H / 4 - 1) ? BT_rn[(i4 + 1) * H + h] : w;  // prefetch next
                #pragma unroll
                for (int j = 0; j < DEG; ++j) {
                    ulonglong2 z = *(const ulonglong2*)&s_znb[j][i4 * 4];  // LDS.128 bcast
                    fma2(acc2[j], w.x, z.x);
                    fma2(acc2[j], w.y, z.y);
                }
                w = wn;
            }
            int skip = need >> 1;
            #pragma unroll
            for (int j = 0; j < DEG; ++j) {
                if (!((skip >> j) & 1)) {
                    float lo, hi; upk2(acc2[j], lo, hi);
                    float tf = btv + wtr.x*s_td[1+j][0] + wtr.y*s_td[1+j][1]
                                   + wtr.z*s_td[1+j][2] + wtr.w*s_td[1+j][3];
                    g_staging[s][1 + j][h] = sigmoidf_(lo + hi + cmn + tf);
                }
            }
        }
        __syncthreads();
        if (tid == 0) red_or_rel(&g_done[s], FULLMASK);
    }
}

// Post pass: one block per step. Hawkes lambdas (pos + 5 neg) and final scatter
// of last-writer rows over the copied z0 region.
__global__ void __launch_bounds__(NTHR) k_post(
    const int* __restrict__ u, const int* __restrict__ u_neg,
    const float* __restrict__ time_bar, const float* __restrict__ time_cur,
    const float* __restrict__ td, const float* __restrict__ z0,
    const float* __restrict__ Wom, const float* __restrict__ bom_p,
    const float* __restrict__ wt_p, const float* __restrict__ alpha_p,
    const float* __restrict__ psi_p, float* __restrict__ out)
{
    const int s = blockIdx.x;
    const int tid = threadIdx.x, lane = tid & 31, wid = tid >> 5;
    const float w_t = *wt_p, alpha = *alpha_p, psi = *psi_p, bom = *bom_p;
    const float inv_psi = 1.0f / (psi + 1e-7f);
    float* outz = out + (BDIM + BDIM * NEGK);

    if (wid < NEGK) {                            // negative lambdas
        int node = u_neg[s * NEGK + wid];
        int sv = g_src[s][NSLOT + wid];
        const float* srcp = (sv >= 0) ? g_staging[sv >> 5][sv & 31]
                                      : (z0 + (size_t)node * H);
        float acc = 0.f;
        for (int i = lane; i < H; i += 32) acc += srcp[i] * Wom[i];
        #pragma unroll
        for (int o = 16; o; o >>= 1) acc += __shfl_down_sync(0xffffffffu, acc, o);
        if (lane == 0) {
            float ts = time_cur[s] - time_bar[(size_t)s * NNODES + node];
            float g = acc + bom + alpha * expf(-w_t * (ts * (1.0f / 86400.0f)));
            float gp = fminf(fmaxf(g * inv_psi, -75.f), 75.f);
            out[BDIM + s * NEGK + wid] = psi * log1pf(expf(gp)) * (1.0f / NEGK);
        }
    } else if (wid == 5) {                       // positive lambda
        int sv = g_src[s][0];
        const float* srcp = (sv >= 0) ? g_staging[sv >> 5][sv & 31]
                                      : (z0 + (size_t)u[s * NSLOT] * H);
        float acc = 0.f;
        for (int i = lane; i < H; i += 32) acc += srcp[i] * Wom[i];
        #pragma unroll
        for (int o = 16; o; o >>= 1) acc += __shfl_down_sync(0xffffffffu, acc, o);
        if (lane == 0) {
            float ts = time_cur[s] - td[s * NSLOT * 4] * (1.0f / 50.0f);
            float g = acc + bom + alpha * expf(-w_t * (ts * (1.0f / 86400.0f)));
            float gp = fminf(fmaxf(g * inv_psi, -75.f), 75.f);
            out[s] = psi * log1pf(expf(gp));
        }
    }

    // scatter: warp handles slots wid, wid+8, wid+16
    for (int w = wid; w < NSLOT; w += 8) {
        int row = u[s * NSLOT + w];
        unsigned hsh = hashrow(row);
        int beste = -1, bestkey = -1;
        for (;;) {
            int cur = g_hrow[hsh];
            if (cur == -1) break;
            if (cur == row) {
                int c = g_hcnt[hsh]; if (c > HK) c = HK;
                for (int i = 0; i < c; ++i) {
                    int e = g_hent[hsh][i];
                    int key = e >> 5;
                    if (key > bestkey) { bestkey = key; beste = e; }
                }
                break;
            }
            hsh = (hsh + 1) & HMASK;
        }
        int prio = (w == 0) ? 16 : (w - 1);
        if (beste == ((s << 10) | (prio << 5) | w)) {   // this (s,w) is the last writer
            const float4* src = (const float4*)g_staging[s][w];
            float4* dst = (float4*)outz + (size_t)row * (H / 4);
            dst[lane]      = src[lane];
            dst[lane + 32] = src[lane + 32];
        }
    }
}

// ------------------------------- launch ------------------------------------
extern "C" void kernel_launch(void* const* d_in, const int* in_sizes, int n_in,
                              void* d_out, int out_size) {
    const int*   u     = (const int*)  d_in[0];
    const float* td    = (const float*)d_in[1];
    const float* tbar  = (const float*)d_in[2];
    const float* tcur  = (const float*)d_in[3];
    // d_in[4] significance, d_in[5] magnitudo: unused by reference
    const int*   uneg  = (const int*)  d_in[6];
    const float* z0    = (const float*)d_in[7];
    const float* Wh    = (const float*)d_in[8];
    const float* bh    = (const float*)d_in[9];
    const float* We2n  = (const float*)d_in[10];
    const float* be2n  = (const float*)d_in[11];
    const float* Wre   = (const float*)d_in[12];
    const float* bre   = (const float*)d_in[13];
    const float* Wrn   = (const float*)d_in[14];
    const float* brn   = (const float*)d_in[15];
    const float* Wt    = (const float*)d_in[16];
    const float* bt    = (const float*)d_in[17];
    const float* Wom   = (const float*)d_in[18];
    const float* bom   = (const float*)d_in[19];
    const float* wt    = (const float*)d_in[20];
    const float* alpha = (const float*)d_in[21];
    const float* psi   = (const float*)d_in[22];
    float* out = (float*)d_out;

    k_clear    <<<(HSIZE + 255) / 256, 256>>>();
    k_transpose<<<256, 256>>>(Wh, We2n, Wre, Wrn);
    k_insert   <<<(BDIM * NSLOT + 255) / 256, 256>>>(u);
    k_resolve  <<<(BDIM * NREAD + 255) / 256, 256>>>(u, uneg, z0, tbar, td);

    int dev = 0, nsm = 148;
    cudaGetDevice(&dev);
    cudaDeviceGetAttribute(&nsm, cudaDevAttrMultiProcessorCount, dev);

    k_main<<<nsm * 2, NTHR>>>(u, td, z0, bh, be2n, bre, brn, Wt, bt, out);

    k_post<<<BDIM, NTHR>>>(u, uneg, tbar, tcur, td, z0,
                           Wom, bom, wt, alpha, psi, out);
}